// round 13
// baseline (speedup 1.0000x reference)
#include <cuda_runtime.h>
#include <math.h>

#define NN 4096
#define HH 64
#define HC 128          // concatenated row width: [h0(64) | h1(64)]
#define G4 256
#define TT 48
#define INP 2
#define PP 12
#define RPB 16          // rows per block
#define NTH 512         // 16 warps
#define ZS 36           // shared z stride per k in floats (32 dup + 4 pad) -> 18 ull (EVEN)
#define CMB (RPB * G4)  // one comb partial: 4096 floats
#define SMEM_FUSED ((256 * ZS + 3 * CMB) * 4)   // z (36.9KB) + 3 comb (48KB) = 84KB
#define MAXNNZ (1 << 21)

typedef unsigned long long ull;

// ---------------- static device scratch ----------------
__device__ float d_hcat[2][NN * HC];        // ping-pong [h0 | h1] per node
__device__ float d_c0[NN * HH];
__device__ float d_c1[NN * HH];
__device__ float d_Xall[NN * (TT * INP)];   // [n][t*2+k]
__device__ float d_AX[NN * (TT * INP)];     // A @ Xall
// W1 rows (z-aligned): 0..63 liWi1 (h0), 64..127 liWh1 (h1), 128..191 gcWi1 (Ah0), 192..255 gcWh1 (Ah1)
__device__ float d_W1[256 * G4];
// W0 rows: half0 = [0..63 liWh0 (h0), 64..65 liWi0 (x)]; half1 = [66..129 gcWh0 (Ah0), 130..131 gcWi0 (Ax)]
__device__ float d_W0[132 * G4];
__device__ float d_b0[G4];
__device__ float d_b1[G4];
__device__ int   d_rowcnt[NN];
__device__ int   d_rowptr[NN + 1];
__device__ float d_dinv[NN];
__device__ int   d_col[MAXNNZ];
__device__ float d_val[MAXNNZ];

// ---------------- helpers ----------------
__device__ __forceinline__ ull fma2(ull a, ull b, ull c) {
    ull d;
    asm("fma.rn.f32x2 %0, %1, %2, %3;" : "=l"(d) : "l"(a), "l"(b), "l"(c));
    return d;
}
__device__ __forceinline__ float sigf(float v) {
    return __fdividef(1.f, 1.f + __expf(-v));
}
__device__ __forceinline__ float tanhfast(float v) {
    return __fmaf_rn(2.f, __fdividef(1.f, 1.f + __expf(-2.f * v)), -1.f);
}

// ---------------- setup kernel 1: degree count + all prep work ----------------
__global__ void k_degprep(const float* __restrict__ adj, const float* __restrict__ x,
                          const float* __restrict__ gcWi0, const float* __restrict__ gcbi0,
                          const float* __restrict__ gcWh0, const float* __restrict__ gcbh0,
                          const float* __restrict__ liWi0, const float* __restrict__ libi0,
                          const float* __restrict__ liWh0, const float* __restrict__ libh0,
                          const float* __restrict__ gcWi1, const float* __restrict__ gcbi1,
                          const float* __restrict__ gcWh1, const float* __restrict__ gcbh1,
                          const float* __restrict__ liWi1, const float* __restrict__ libi1,
                          const float* __restrict__ liWh1, const float* __restrict__ libh1) {
    int i = blockIdx.x;
    int tid = threadIdx.x;
    // ---- degree + nnz count for row i ----
    {
        const float* row = adj + (size_t)i * NN;
        int cnt = 0; float deg = 0.f;
        for (int j = tid; j < NN; j += 256) {
            float a = row[j];
            if (j == i) a += 1.f;
            if (a != 0.f) { cnt++; deg += a; }
        }
        __shared__ int   scnt[256];
        __shared__ float sdeg[256];
        scnt[tid] = cnt; sdeg[tid] = deg;
        __syncthreads();
        for (int s = 128; s > 0; s >>= 1) {
            if (tid < s) { scnt[tid] += scnt[tid + s]; sdeg[tid] += sdeg[tid + s]; }
            __syncthreads();
        }
        if (tid == 0) {
            d_rowcnt[i] = scnt[0];
            d_dinv[i] = rsqrtf(sdeg[0]);
        }
    }
    // ---- prep work (grid covers 1M ids) ----
    int id = i * 256 + tid;
    if (id < NN * (TT * INP)) {
        int n = id / (TT * INP), c = id % (TT * INP);
        int t = c >> 1, k = c & 1;
        d_Xall[id] = x[t * (NN * INP) + n * INP + k];
    }
    if (id < NN * HC) {
        d_hcat[0][id] = 0.f;        // h1 half matters; h0 half overwritten later
    }
    if (id < NN * HH) {
        d_c1[id] = 0.f;
    }
    if (id < 256 * G4) {
        int k = id >> 8, c = id & 255;
        float w1;
        if (k < 64)       w1 = liWi1[k * G4 + c];          // z: h0
        else if (k < 128) w1 = liWh1[(k - 64) * G4 + c];   // z: h1
        else if (k < 192) w1 = gcWi1[(k - 128) * G4 + c];  // z: A@h0
        else              w1 = gcWh1[(k - 192) * G4 + c];  // z: A@h1
        d_W1[id] = w1;
        if (k < 132) {
            float w0;
            if (k < 64)       w0 = liWh0[k * G4 + c];          // half0: h0
            else if (k < 66)  w0 = liWi0[(k - 64) * G4 + c];   // half0: x
            else if (k < 130) w0 = gcWh0[(k - 66) * G4 + c];   // half1: A@h0
            else              w0 = gcWi0[(k - 130) * G4 + c];  // half1: Ax
            d_W0[k * G4 + c] = w0;
        }
        if (id < G4) {
            d_b0[id] = gcbi0[id] + gcbh0[id] + libi0[id] + libh0[id];
            d_b1[id] = gcbi1[id] + gcbh1[id] + libi1[id] + libh1[id];
        }
    }
}

// ---------------- setup kernel 2: exclusive scan ----------------
__global__ void k_scan() {
    __shared__ int ssum[1024];
    int t = threadIdx.x;
    int c0 = d_rowcnt[4 * t], c1 = d_rowcnt[4 * t + 1],
        c2 = d_rowcnt[4 * t + 2], c3 = d_rowcnt[4 * t + 3];
    int s = c0 + c1 + c2 + c3;
    ssum[t] = s;
    __syncthreads();
    for (int off = 1; off < 1024; off <<= 1) {
        int v = (t >= off) ? ssum[t - off] : 0;
        __syncthreads();
        ssum[t] += v;
        __syncthreads();
    }
    int excl = ssum[t] - s;
    d_rowptr[4 * t]     = excl;
    d_rowptr[4 * t + 1] = excl + c0;
    d_rowptr[4 * t + 2] = excl + c0 + c1;
    d_rowptr[4 * t + 3] = excl + c0 + c1 + c2;
    if (t == 1023) d_rowptr[NN] = ssum[1023];
}

// ---------------- setup kernel 3: CSR fill + AX spmm (own row) + first-step cell0 ----------------
__global__ void k_fillx(const float* __restrict__ adj, const float* __restrict__ x) {
    int i = blockIdx.x;
    int tid = threadIdx.x;
    const float* row = adj + (size_t)i * NN;
    float di = d_dinv[i];
    int cnt = 0;
    for (int j = tid * 16; j < tid * 16 + 16; j++) {
        float a = row[j] + ((j == i) ? 1.f : 0.f);
        if (a != 0.f) cnt++;
    }
    __shared__ int soff[256];
    __shared__ float sax[2];
    soff[tid] = cnt;
    __syncthreads();
    for (int off = 1; off < 256; off <<= 1) {
        int v = (tid >= off) ? soff[tid - off] : 0;
        __syncthreads();
        soff[tid] += v;
        __syncthreads();
    }
    int pos = d_rowptr[i] + soff[tid] - cnt;
    for (int j = tid * 16; j < tid * 16 + 16; j++) {
        float a = row[j] + ((j == i) ? 1.f : 0.f);
        if (a != 0.f) {
            d_col[pos] = j;
            d_val[pos] = di * a * d_dinv[j];
            pos++;
        }
    }
    __syncthreads();   // row i's CSR fully written, visible to this block

    // ---- AX row i (threads 0..95) ----
    if (tid < TT * INP) {
        int p0 = d_rowptr[i], p1 = d_rowptr[i + 1];
        float acc = 0.f;
        for (int p = p0; p < p1; p++) {
            acc += d_val[p] * d_Xall[d_col[p] * (TT * INP) + tid];
        }
        d_AX[i * (TT * INP) + tid] = acc;
        if (tid < 2) sax[tid] = acc;
    }
    __syncthreads();

    // ---- first-step cell0 for node i (h0=Ah0=0 so comb = b0 + x-part) ----
    // x rows in NEW W0 layout: liWi0 = rows 64,65 ; gcWi0 = rows 130,131
    if (tid < HH) {
        int j = tid;
        float x0  = x[i * INP];
        float x1  = x[i * INP + 1];
        float ax0 = sax[0];
        float ax1 = sax[1];
        float gv[4];
        #pragma unroll
        for (int q = 0; q < 4; q++) {
            int c = q * 64 + j;
            gv[q] = d_b0[c]
                  + x0  * d_W0[64 * G4 + c]  + x1  * d_W0[65 * G4 + c]
                  + ax0 * d_W0[130 * G4 + c] + ax1 * d_W0[131 * G4 + c];
        }
        float nc = sigf(gv[0]) * tanhfast(gv[3]);
        float nh = sigf(gv[2]) * tanhfast(nc);
        d_c0[i * HH + j] = nc;
        d_hcat[0][i * HC + j] = nh;
    }
}

// ---------------- GEMM partial: 8 warp-slots, KN k-rows, ull2 broadcast z ----------------
// ws in [0,8): rows r0=(ws&3)*4 .. +3, cols c0=(ws>>2)*128 + lane*4 .. +3
// W already offset to its first row; z rows start at zrow0.
template <int KN, bool BIAS>
__device__ __forceinline__ void gemm_part(const float* __restrict__ sh, float* __restrict__ comb,
                                          const float* __restrict__ W,
                                          const float* __restrict__ bb,
                                          int zrow0, int ws, int lane) {
    int r0 = (ws & 3) << 2;
    int c0 = ((ws >> 2) << 7) + (lane << 2);
    const float* Wp = W + c0;
    const ull* zz = (const ull*)sh + zrow0 * 18 + r0;

    ull a00, a01, a10, a11, a20, a21, a30, a31;
    if (BIAS) {
        ulonglong2 b2 = *(const ulonglong2*)(bb + c0);
        a00 = b2.x; a01 = b2.y; a10 = b2.x; a11 = b2.y;
        a20 = b2.x; a21 = b2.y; a30 = b2.x; a31 = b2.y;
    } else {
        a00 = a01 = a10 = a11 = a20 = a21 = a30 = a31 = 0ull;
    }

    #pragma unroll 4
    for (int k = 0; k < KN; k++) {
        ulonglong2 w2 = *(const ulonglong2*)(Wp + k * G4);
        ulonglong2 zA = *(const ulonglong2*)(zz + k * 18);       // rows r0, r0+1 (broadcast)
        ulonglong2 zB = *(const ulonglong2*)(zz + k * 18 + 2);   // rows r0+2, r0+3
        a00 = fma2(zA.x, w2.x, a00); a01 = fma2(zA.x, w2.y, a01);
        a10 = fma2(zA.y, w2.x, a10); a11 = fma2(zA.y, w2.y, a11);
        a20 = fma2(zB.x, w2.x, a20); a21 = fma2(zB.x, w2.y, a21);
        a30 = fma2(zB.y, w2.x, a30); a31 = fma2(zB.y, w2.y, a31);
    }
    float* base = comb + r0 * G4 + c0;
    *(ulonglong2*)(base)          = make_ulonglong2(a00, a01);
    *(ulonglong2*)(base + G4)     = make_ulonglong2(a10, a11);
    *(ulonglong2*)(base + 2 * G4) = make_ulonglong2(a20, a21);
    *(ulonglong2*)(base + 3 * G4) = make_ulonglong2(a30, a31);
}

// ---------------- fused step: cell1(t) then cell0(t+1), warp-specialized ----------------
__global__ void __launch_bounds__(NTH, 2) k_fused(const float* __restrict__ x, int t) {
    extern __shared__ float sh[];
    float* combP0 = sh + 256 * ZS;
    float* combP1 = combP0 + CMB;
    float* combP2 = combP0 + 2 * CMB;
    int tid = threadIdx.x;
    int n0 = blockIdx.x * RPB;
    int cur = t & 1, nxt = cur ^ 1;
    const float* __restrict__ g = d_hcat[cur];
    int w = tid >> 5, lane = tid & 31;

    // ---- stage plain z: rows 0..127 = [h0 | h1] of own 16 nodes ----
    #pragma unroll
    for (int i = 0; i < 4; i++) {
        int e = i * NTH + tid;          // [0, 2048) = 16 rows x 128 k
        int r = e >> 7, k = e & 127;
        float v = g[(n0 + r) * HC + k];
        *(float2*)(sh + k * ZS + 2 * r) = make_float2(v, v);
    }
    __syncthreads();

    // ---- phase A: warps 0..7 GEMM plain k (0..127) | warps 8..15 gather -> z rows 128..255 ----
    if (w < 8) {
        gemm_part<128, true>(sh, combP0, d_W1, d_b1, 0, w, lane);
    } else {
        int w2 = w - 8;
        int koff = 128 + 4 * lane;      // lane<16 -> A@h0 rows, lane>=16 -> A@h1 rows
        const float* gl = g + 4 * lane;
        #pragma unroll
        for (int half = 0; half < 2; half++) {
            int rr = w2 + half * 8;
            int n = n0 + rr;
            int p = d_rowptr[n], p1 = d_rowptr[n + 1];
            float a0 = 0.f, a1 = 0.f, a2 = 0.f, a3 = 0.f;
            for (; p + 4 <= p1; p += 4) {
                int   m0 = d_col[p],     m1 = d_col[p + 1];
                int   m2 = d_col[p + 2], m3 = d_col[p + 3];
                float v0 = d_val[p],     v1 = d_val[p + 1];
                float v2 = d_val[p + 2], v3 = d_val[p + 3];
                float4 A = *(const float4*)(gl + m0 * HC);
                float4 B = *(const float4*)(gl + m1 * HC);
                float4 C = *(const float4*)(gl + m2 * HC);
                float4 D = *(const float4*)(gl + m3 * HC);
                a0 += v0 * A.x; a1 += v0 * A.y; a2 += v0 * A.z; a3 += v0 * A.w;
                a0 += v1 * B.x; a1 += v1 * B.y; a2 += v1 * B.z; a3 += v1 * B.w;
                a0 += v2 * C.x; a1 += v2 * C.y; a2 += v2 * C.z; a3 += v2 * C.w;
                a0 += v3 * D.x; a1 += v3 * D.y; a2 += v3 * D.z; a3 += v3 * D.w;
            }
            for (; p < p1; p++) {
                int m = d_col[p];
                float v = d_val[p];
                float4 A = *(const float4*)(gl + m * HC);
                a0 += v * A.x; a1 += v * A.y; a2 += v * A.z; a3 += v * A.w;
            }
            *(float2*)(sh + (koff + 0) * ZS + 2 * rr) = make_float2(a0, a0);
            *(float2*)(sh + (koff + 1) * ZS + 2 * rr) = make_float2(a1, a1);
            *(float2*)(sh + (koff + 2) * ZS + 2 * rr) = make_float2(a2, a2);
            *(float2*)(sh + (koff + 3) * ZS + 2 * rr) = make_float2(a3, a3);
        }
    }
    __syncthreads();

    // ---- phase B: all 16 warps GEMM gathered k (128..255), two 64-k quarters ----
    {
        int q = w >> 3, ws = w & 7;
        float* dst = (q == 0) ? combP1 : combP2;
        gemm_part<64, false>(sh, dst, d_W1 + (128 + 64 * q) * G4, (const float*)0,
                             128 + 64 * q, ws, lane);
    }
    __syncthreads();

    // ---- gates cell1: sum 3 partials -> h1(t), c1 ; stage x for cell0 ----
    #pragma unroll
    for (int i = 0; i < 2; i++) {
        int e = i * NTH + tid;          // 1024 = 16 rows * 64
        int r = e >> 6, j = e & 63;
        float ig = combP0[r * G4 + j]       + combP1[r * G4 + j]       + combP2[r * G4 + j];
        float fg = combP0[r * G4 + 64 + j]  + combP1[r * G4 + 64 + j]  + combP2[r * G4 + 64 + j];
        float og = combP0[r * G4 + 128 + j] + combP1[r * G4 + 128 + j] + combP2[r * G4 + 128 + j];
        float gg = combP0[r * G4 + 192 + j] + combP1[r * G4 + 192 + j] + combP2[r * G4 + 192 + j];
        int n = n0 + r;
        float cold = d_c1[n * HH + j];
        float nc = sigf(fg) * cold + sigf(ig) * tanhfast(gg);
        float nh = sigf(og) * tanhfast(nc);
        d_c1[n * HH + j] = nc;
        d_hcat[nxt][n * HC + 64 + j] = nh;
    }
    if (t + 1 < TT && tid < RPB) {
        int n = n0 + tid;
        float x0  = x[(t + 1) * (NN * INP) + n * INP];
        float x1  = x[(t + 1) * (NN * INP) + n * INP + 1];
        float ax0 = d_AX[n * (TT * INP) + 2 * (t + 1)];
        float ax1 = d_AX[n * (TT * INP) + 2 * (t + 1) + 1];
        *(float2*)(sh + 64 * ZS + 2 * tid)  = make_float2(x0, x0);    // z row 64  <- x0
        *(float2*)(sh + 65 * ZS + 2 * tid)  = make_float2(x1, x1);    // z row 65  <- x1
        *(float2*)(sh + 192 * ZS + 2 * tid) = make_float2(ax0, ax0);  // z row 192 <- ax0
        *(float2*)(sh + 193 * ZS + 2 * tid) = make_float2(ax1, ax1);  // z row 193 <- ax1
    }
    __syncthreads();

    // ---- cell0(t+1): split-K over {rows 0..65} and {rows 128..193} ----
    if (t + 1 < TT) {
        {
            int half = w >> 3, ws = w & 7;
            if (half == 0) {
                gemm_part<66, true>(sh, combP0, d_W0, d_b0, 0, ws, lane);
            } else {
                gemm_part<66, false>(sh, combP1, d_W0 + 66 * G4, (const float*)0, 128, ws, lane);
            }
        }
        __syncthreads();
        // gates cell0: sum 2 partials -> h0(t+1), c0
        #pragma unroll
        for (int i = 0; i < 2; i++) {
            int e = i * NTH + tid;
            int r = e >> 6, j = e & 63;
            float ig = combP0[r * G4 + j]       + combP1[r * G4 + j];
            float fg = combP0[r * G4 + 64 + j]  + combP1[r * G4 + 64 + j];
            float og = combP0[r * G4 + 128 + j] + combP1[r * G4 + 128 + j];
            float gg = combP0[r * G4 + 192 + j] + combP1[r * G4 + 192 + j];
            int n = n0 + r;
            float cold = d_c0[n * HH + j];
            float nc = sigf(fg) * cold + sigf(ig) * tanhfast(gg);
            float nh = sigf(og) * tanhfast(nc);
            d_c0[n * HH + j] = nc;
            d_hcat[nxt][n * HC + j] = nh;
        }
    }
}

// ---------------- output projection ----------------
__global__ void k_out(const float* __restrict__ outW, const float* __restrict__ outb,
                      float* __restrict__ out) {
    int gidx = blockIdx.x * blockDim.x + threadIdx.x;
    if (gidx >= NN * PP) return;
    int n = gidx / PP, p = gidx % PP;
    const float* h = d_hcat[TT & 1] + n * HC + 64;
    float acc = outb[p];
    #pragma unroll
    for (int k = 0; k < HH; k++) acc += h[k] * outW[k * PP + p];
    out[gidx] = acc;
}

extern "C" void kernel_launch(void* const* d_in, const int* in_sizes, int n_in,
                              void* d_out, int out_size) {
    const float* x     = (const float*)d_in[0];
    const float* adj   = (const float*)d_in[1];
    const float* gcWi0 = (const float*)d_in[2];
    const float* gcbi0 = (const float*)d_in[3];
    const float* gcWh0 = (const float*)d_in[4];
    const float* gcbh0 = (const float*)d_in[5];
    const float* liWi0 = (const float*)d_in[6];
    const float* libi0 = (const float*)d_in[7];
    const float* liWh0 = (const float*)d_in[8];
    const float* libh0 = (const float*)d_in[9];
    const float* gcWi1 = (const float*)d_in[10];
    const float* gcbi1 = (const float*)d_in[11];
    const float* gcWh1 = (const float*)d_in[12];
    const float* gcbh1 = (const float*)d_in[13];
    const float* liWi1 = (const float*)d_in[14];
    const float* libi1 = (const float*)d_in[15];
    const float* liWh1 = (const float*)d_in[16];
    const float* libh1 = (const float*)d_in[17];
    const float* outW  = (const float*)d_in[18];
    const float* outb  = (const float*)d_in[19];
    float* out = (float*)d_out;

    static int smem_set = 0;
    if (!smem_set) {
        cudaFuncSetAttribute(k_fused, cudaFuncAttributeMaxDynamicSharedMemorySize, SMEM_FUSED);
        smem_set = 1;
    }

    k_degprep<<<4096, 256>>>(adj, x, gcWi0, gcbi0, gcWh0, gcbh0, liWi0, libi0, liWh0, libh0,
                             gcWi1, gcbi1, gcWh1, gcbh1, liWi1, libi1, liWh1, libh1);
    k_scan<<<1, 1024>>>();
    k_fillx<<<NN, 256>>>(adj, x);
    for (int t = 0; t < TT; t++) {
        k_fused<<<NN / RPB, NTH, SMEM_FUSED>>>(x, t);
    }
    k_out<<<(NN * PP + 255) / 256, 256>>>(outW, outb, out);
}

// round 14
// speedup vs baseline: 1.0032x; 1.0032x over previous
#include <cuda_runtime.h>
#include <math.h>

#define NN 4096
#define HH 64
#define HC 128          // concatenated row width: [h0(64) | h1(64)]
#define G4 256
#define TT 48
#define INP 2
#define PP 12
#define RPB 16          // rows per block
#define NTH 512         // 16 warps
#define ZS 36           // shared z stride per k in floats (32 dup + 4 pad) -> 18 ull (EVEN)
#define ZROWS 260       // h0(64) Ah0(64) x(4) h1(64) Ah1(64)
#define CMB (RPB * G4)  // one comb partial: 4096 floats
#define SMEM_FUSED ((ZROWS * ZS + 4 * CMB) * 4)   // z (36.6KB) + 4 comb (64KB) = 100.6KB
#define MAXNNZ (1 << 21)

typedef unsigned long long ull;

// ---------------- static device scratch ----------------
__device__ float d_hcat[2][NN * HC];        // ping-pong [h0 | h1] per node
__device__ float d_c0[NN * HH];
__device__ float d_c1[NN * HH];
__device__ float d_Xall[NN * (TT * INP)];   // [n][t*2+k]
__device__ float d_AX[NN * (TT * INP)];     // A @ Xall
// W1 rows (z-aligned): 0..63 liWi1 (h0), 64..127 gcWi1 (Ah0), 128..191 liWh1 (h1), 192..255 gcWh1 (Ah1)
__device__ float d_W1[256 * G4];
// W0 rows: 0..63 liWh0 (h0), 64..127 gcWh0 (Ah0), 128..129 liWi0 (x), 130..131 gcWi0 (Ax)
__device__ float d_W0[132 * G4];
__device__ float d_b0[G4];
__device__ float d_b1[G4];
__device__ int   d_rowcnt[NN];
__device__ int   d_rowptr[NN + 1];
__device__ float d_dinv[NN];
__device__ int   d_col[MAXNNZ];
__device__ float d_val[MAXNNZ];

// ---------------- helpers ----------------
__device__ __forceinline__ ull fma2(ull a, ull b, ull c) {
    ull d;
    asm("fma.rn.f32x2 %0, %1, %2, %3;" : "=l"(d) : "l"(a), "l"(b), "l"(c));
    return d;
}
__device__ __forceinline__ float sigf(float v) {
    return __fdividef(1.f, 1.f + __expf(-v));
}
__device__ __forceinline__ float tanhfast(float v) {
    return __fmaf_rn(2.f, __fdividef(1.f, 1.f + __expf(-2.f * v)), -1.f);
}

// ---------------- setup kernel 1: degree count + all prep work ----------------
__global__ void k_degprep(const float* __restrict__ adj, const float* __restrict__ x,
                          const float* __restrict__ gcWi0, const float* __restrict__ gcbi0,
                          const float* __restrict__ gcWh0, const float* __restrict__ gcbh0,
                          const float* __restrict__ liWi0, const float* __restrict__ libi0,
                          const float* __restrict__ liWh0, const float* __restrict__ libh0,
                          const float* __restrict__ gcWi1, const float* __restrict__ gcbi1,
                          const float* __restrict__ gcWh1, const float* __restrict__ gcbh1,
                          const float* __restrict__ liWi1, const float* __restrict__ libi1,
                          const float* __restrict__ liWh1, const float* __restrict__ libh1) {
    int i = blockIdx.x;
    int tid = threadIdx.x;
    // ---- degree + nnz count for row i ----
    {
        const float* row = adj + (size_t)i * NN;
        int cnt = 0; float deg = 0.f;
        for (int j = tid; j < NN; j += 256) {
            float a = row[j];
            if (j == i) a += 1.f;
            if (a != 0.f) { cnt++; deg += a; }
        }
        __shared__ int   scnt[256];
        __shared__ float sdeg[256];
        scnt[tid] = cnt; sdeg[tid] = deg;
        __syncthreads();
        for (int s = 128; s > 0; s >>= 1) {
            if (tid < s) { scnt[tid] += scnt[tid + s]; sdeg[tid] += sdeg[tid + s]; }
            __syncthreads();
        }
        if (tid == 0) {
            d_rowcnt[i] = scnt[0];
            d_dinv[i] = rsqrtf(sdeg[0]);
        }
    }
    // ---- prep work (grid covers 1M ids) ----
    int id = i * 256 + tid;
    if (id < NN * (TT * INP)) {
        int n = id / (TT * INP), c = id % (TT * INP);
        int t = c >> 1, k = c & 1;
        d_Xall[id] = x[t * (NN * INP) + n * INP + k];
    }
    if (id < NN * HC) {
        d_hcat[0][id] = 0.f;        // h1 half matters; h0 half overwritten later
    }
    if (id < NN * HH) {
        d_c1[id] = 0.f;
    }
    if (id < 256 * G4) {
        int k = id >> 8, c = id & 255;
        float w1;
        if (k < 64)       w1 = liWi1[k * G4 + c];          // z: h0
        else if (k < 128) w1 = gcWi1[(k - 64) * G4 + c];   // z: A@h0
        else if (k < 192) w1 = liWh1[(k - 128) * G4 + c];  // z: h1
        else              w1 = gcWh1[(k - 192) * G4 + c];  // z: A@h1
        d_W1[id] = w1;
        if (k < 132) {
            float w0;
            if (k < 64)       w0 = liWh0[k * G4 + c];          // z: h0
            else if (k < 128) w0 = gcWh0[(k - 64) * G4 + c];   // z: A@h0
            else if (k < 130) w0 = liWi0[(k - 128) * G4 + c];  // z: x
            else              w0 = gcWi0[(k - 130) * G4 + c];  // z: Ax
            d_W0[k * G4 + c] = w0;
        }
        if (id < G4) {
            d_b0[id] = gcbi0[id] + gcbh0[id] + libi0[id] + libh0[id];
            d_b1[id] = gcbi1[id] + gcbh1[id] + libi1[id] + libh1[id];
        }
    }
}

// ---------------- setup kernel 2: exclusive scan ----------------
__global__ void k_scan() {
    __shared__ int ssum[1024];
    int t = threadIdx.x;
    int c0 = d_rowcnt[4 * t], c1 = d_rowcnt[4 * t + 1],
        c2 = d_rowcnt[4 * t + 2], c3 = d_rowcnt[4 * t + 3];
    int s = c0 + c1 + c2 + c3;
    ssum[t] = s;
    __syncthreads();
    for (int off = 1; off < 1024; off <<= 1) {
        int v = (t >= off) ? ssum[t - off] : 0;
        __syncthreads();
        ssum[t] += v;
        __syncthreads();
    }
    int excl = ssum[t] - s;
    d_rowptr[4 * t]     = excl;
    d_rowptr[4 * t + 1] = excl + c0;
    d_rowptr[4 * t + 2] = excl + c0 + c1;
    d_rowptr[4 * t + 3] = excl + c0 + c1 + c2;
    if (t == 1023) d_rowptr[NN] = ssum[1023];
}

// ---------------- setup kernel 3: CSR fill + AX spmm (own row) + first-step cell0 ----------------
__global__ void k_fillx(const float* __restrict__ adj, const float* __restrict__ x) {
    int i = blockIdx.x;
    int tid = threadIdx.x;
    const float* row = adj + (size_t)i * NN;
    float di = d_dinv[i];
    int cnt = 0;
    for (int j = tid * 16; j < tid * 16 + 16; j++) {
        float a = row[j] + ((j == i) ? 1.f : 0.f);
        if (a != 0.f) cnt++;
    }
    __shared__ int soff[256];
    __shared__ float sax[2];
    soff[tid] = cnt;
    __syncthreads();
    for (int off = 1; off < 256; off <<= 1) {
        int v = (tid >= off) ? soff[tid - off] : 0;
        __syncthreads();
        soff[tid] += v;
        __syncthreads();
    }
    int pos = d_rowptr[i] + soff[tid] - cnt;
    for (int j = tid * 16; j < tid * 16 + 16; j++) {
        float a = row[j] + ((j == i) ? 1.f : 0.f);
        if (a != 0.f) {
            d_col[pos] = j;
            d_val[pos] = di * a * d_dinv[j];
            pos++;
        }
    }
    __syncthreads();   // row i's CSR fully written, visible to this block

    // ---- AX row i (threads 0..95) ----
    if (tid < TT * INP) {
        int p0 = d_rowptr[i], p1 = d_rowptr[i + 1];
        float acc = 0.f;
        for (int p = p0; p < p1; p++) {
            acc += d_val[p] * d_Xall[d_col[p] * (TT * INP) + tid];
        }
        d_AX[i * (TT * INP) + tid] = acc;
        if (tid < 2) sax[tid] = acc;
    }
    __syncthreads();

    // ---- first-step cell0 for node i (h0=Ah0=0 so comb = b0 + x-part) ----
    if (tid < HH) {
        int j = tid;
        float x0  = x[i * INP];
        float x1  = x[i * INP + 1];
        float ax0 = sax[0];
        float ax1 = sax[1];
        float gv[4];
        #pragma unroll
        for (int q = 0; q < 4; q++) {
            int c = q * 64 + j;
            gv[q] = d_b0[c]
                  + x0  * d_W0[128 * G4 + c] + x1  * d_W0[129 * G4 + c]
                  + ax0 * d_W0[130 * G4 + c] + ax1 * d_W0[131 * G4 + c];
        }
        float nc = sigf(gv[0]) * tanhfast(gv[3]);
        float nh = sigf(gv[2]) * tanhfast(nc);
        d_c0[i * HH + j] = nc;
        d_hcat[0][i * HC + j] = nh;
    }
}

// ---------------- GEMM partial: 8 warp-slots, KN k-rows, ull2 broadcast z ----------------
// ws in [0,8): rows r0=(ws&3)*4 .. +3, cols c0=(ws>>2)*128 + lane*4 .. +3
template <int KN, bool BIAS>
__device__ __forceinline__ void gemm_part(const float* __restrict__ sh, float* __restrict__ comb,
                                          const float* __restrict__ W,
                                          const float* __restrict__ bb,
                                          int zrow0, int ws, int lane) {
    int r0 = (ws & 3) << 2;
    int c0 = ((ws >> 2) << 7) + (lane << 2);
    const float* Wp = W + c0;
    const ull* zz = (const ull*)sh + zrow0 * 18 + r0;

    ull a00, a01, a10, a11, a20, a21, a30, a31;
    if (BIAS) {
        ulonglong2 b2 = *(const ulonglong2*)(bb + c0);
        a00 = b2.x; a01 = b2.y; a10 = b2.x; a11 = b2.y;
        a20 = b2.x; a21 = b2.y; a30 = b2.x; a31 = b2.y;
    } else {
        a00 = a01 = a10 = a11 = a20 = a21 = a30 = a31 = 0ull;
    }

    #pragma unroll 4
    for (int k = 0; k < KN; k++) {
        ulonglong2 w2 = *(const ulonglong2*)(Wp + k * G4);
        ulonglong2 zA = *(const ulonglong2*)(zz + k * 18);       // rows r0, r0+1 (broadcast)
        ulonglong2 zB = *(const ulonglong2*)(zz + k * 18 + 2);   // rows r0+2, r0+3
        a00 = fma2(zA.x, w2.x, a00); a01 = fma2(zA.x, w2.y, a01);
        a10 = fma2(zA.y, w2.x, a10); a11 = fma2(zA.y, w2.y, a11);
        a20 = fma2(zB.x, w2.x, a20); a21 = fma2(zB.x, w2.y, a21);
        a30 = fma2(zB.y, w2.x, a30); a31 = fma2(zB.y, w2.y, a31);
    }
    float* base = comb + r0 * G4 + c0;
    *(ulonglong2*)(base)          = make_ulonglong2(a00, a01);
    *(ulonglong2*)(base + G4)     = make_ulonglong2(a10, a11);
    *(ulonglong2*)(base + 2 * G4) = make_ulonglong2(a20, a21);
    *(ulonglong2*)(base + 3 * G4) = make_ulonglong2(a30, a31);
}

// ---------------- fused step: cell1(t) + cell0(t+1), single GEMM phase ----------------
// z rows: 0..63 h0 | 64..127 A@h0 | 128..131 x(t+1),Ax(t+1) | 132..195 h1 | 196..259 A@h1
__global__ void __launch_bounds__(NTH, 2) k_fused(const float* __restrict__ x, int t) {
    extern __shared__ float sh[];
    float* combA = sh + ZROWS * ZS;     // cell1 half0
    float* combB = combA + CMB;         // cell1 half1
    float* combC = combA + 2 * CMB;     // cell0 half0
    float* combD = combA + 3 * CMB;     // cell0 half1
    int tid = threadIdx.x;
    int n0 = blockIdx.x * RPB;
    int cur = t & 1, nxt = cur ^ 1;
    const float* __restrict__ g = d_hcat[cur];
    int w = tid >> 5, lane = tid & 31;
    bool more = (t + 1 < TT);

    // ---- phase 1: stage plain z + x, and gather ----
    #pragma unroll
    for (int i = 0; i < 2; i++) {
        int e = i * NTH + tid;          // [0, 1024) = 16 rows x 64 k
        int r = e >> 6, k = e & 63;
        float v0 = g[(n0 + r) * HC + k];        // h0 -> row k
        float v1 = g[(n0 + r) * HC + 64 + k];   // h1 -> row 132+k
        *(float2*)(sh + k * ZS + 2 * r)         = make_float2(v0, v0);
        *(float2*)(sh + (132 + k) * ZS + 2 * r) = make_float2(v1, v1);
    }
    if (more && tid < RPB) {
        int n = n0 + tid;
        float x0  = x[(t + 1) * (NN * INP) + n * INP];
        float x1  = x[(t + 1) * (NN * INP) + n * INP + 1];
        float ax0 = d_AX[n * (TT * INP) + 2 * (t + 1)];
        float ax1 = d_AX[n * (TT * INP) + 2 * (t + 1) + 1];
        *(float2*)(sh + 128 * ZS + 2 * tid) = make_float2(x0, x0);
        *(float2*)(sh + 129 * ZS + 2 * tid) = make_float2(x1, x1);
        *(float2*)(sh + 130 * ZS + 2 * tid) = make_float2(ax0, ax0);
        *(float2*)(sh + 131 * ZS + 2 * tid) = make_float2(ax1, ax1);
    }
    // gather: 16 warps x 1 row; lane<16 -> A@h0 (rows 64+4l), lane>=16 -> A@h1 (rows 132+4l)
    {
        int koff = (lane < 16) ? (64 + 4 * lane) : (132 + 4 * lane);
        const float* gl = g + 4 * lane;
        int n = n0 + w;
        int p = d_rowptr[n], p1 = d_rowptr[n + 1];
        float a0 = 0.f, a1 = 0.f, a2 = 0.f, a3 = 0.f;
        for (; p + 4 <= p1; p += 4) {
            int   m0 = d_col[p],     m1 = d_col[p + 1];
            int   m2 = d_col[p + 2], m3 = d_col[p + 3];
            float v0 = d_val[p],     v1 = d_val[p + 1];
            float v2 = d_val[p + 2], v3 = d_val[p + 3];
            float4 A = *(const float4*)(gl + m0 * HC);
            float4 B = *(const float4*)(gl + m1 * HC);
            float4 C = *(const float4*)(gl + m2 * HC);
            float4 D = *(const float4*)(gl + m3 * HC);
            a0 += v0 * A.x; a1 += v0 * A.y; a2 += v0 * A.z; a3 += v0 * A.w;
            a0 += v1 * B.x; a1 += v1 * B.y; a2 += v1 * B.z; a3 += v1 * B.w;
            a0 += v2 * C.x; a1 += v2 * C.y; a2 += v2 * C.z; a3 += v2 * C.w;
            a0 += v3 * D.x; a1 += v3 * D.y; a2 += v3 * D.z; a3 += v3 * D.w;
        }
        for (; p < p1; p++) {
            int m = d_col[p];
            float v = d_val[p];
            float4 A = *(const float4*)(gl + m * HC);
            a0 += v * A.x; a1 += v * A.y; a2 += v * A.z; a3 += v * A.w;
        }
        *(float2*)(sh + (koff + 0) * ZS + 2 * w) = make_float2(a0, a0);
        *(float2*)(sh + (koff + 1) * ZS + 2 * w) = make_float2(a1, a1);
        *(float2*)(sh + (koff + 2) * ZS + 2 * w) = make_float2(a2, a2);
        *(float2*)(sh + (koff + 3) * ZS + 2 * w) = make_float2(a3, a3);
    }
    __syncthreads();

    // ---- phase 2: both GEMMs, one stream per warp ----
    {
        int half = w >> 3, ws = w & 7;
        if (half == 0) {
            gemm_part<128, true>(sh, combA, d_W1, d_b1, 0, ws, lane);
            if (more) gemm_part<66, true>(sh, combC, d_W0, d_b0, 0, ws, lane);
        } else {
            gemm_part<128, false>(sh, combB, d_W1 + 128 * G4, (const float*)0, 132, ws, lane);
            if (more) gemm_part<66, false>(sh, combD, d_W0 + 66 * G4, (const float*)0, 66, ws, lane);
        }
    }
    __syncthreads();

    // ---- phase 3: gates for both cells ----
    #pragma unroll
    for (int i = 0; i < 2; i++) {
        int e = i * NTH + tid;          // 1024 = 16 rows * 64
        int r = e >> 6, j = e & 63;
        float ig = combA[r * G4 + j]       + combB[r * G4 + j];
        float fg = combA[r * G4 + 64 + j]  + combB[r * G4 + 64 + j];
        float og = combA[r * G4 + 128 + j] + combB[r * G4 + 128 + j];
        float gg = combA[r * G4 + 192 + j] + combB[r * G4 + 192 + j];
        int n = n0 + r;
        float cold = d_c1[n * HH + j];
        float nc = sigf(fg) * cold + sigf(ig) * tanhfast(gg);
        float nh = sigf(og) * tanhfast(nc);
        d_c1[n * HH + j] = nc;
        d_hcat[nxt][n * HC + 64 + j] = nh;
    }
    if (more) {
        #pragma unroll
        for (int i = 0; i < 2; i++) {
            int e = i * NTH + tid;
            int r = e >> 6, j = e & 63;
            float ig = combC[r * G4 + j]       + combD[r * G4 + j];
            float fg = combC[r * G4 + 64 + j]  + combD[r * G4 + 64 + j];
            float og = combC[r * G4 + 128 + j] + combD[r * G4 + 128 + j];
            float gg = combC[r * G4 + 192 + j] + combD[r * G4 + 192 + j];
            int n = n0 + r;
            float cold = d_c0[n * HH + j];
            float nc = sigf(fg) * cold + sigf(ig) * tanhfast(gg);
            float nh = sigf(og) * tanhfast(nc);
            d_c0[n * HH + j] = nc;
            d_hcat[nxt][n * HC + j] = nh;
        }
    }
}

// ---------------- output projection ----------------
__global__ void k_out(const float* __restrict__ outW, const float* __restrict__ outb,
                      float* __restrict__ out) {
    int gidx = blockIdx.x * blockDim.x + threadIdx.x;
    if (gidx >= NN * PP) return;
    int n = gidx / PP, p = gidx % PP;
    const float* h = d_hcat[TT & 1] + n * HC + 64;
    float acc = outb[p];
    #pragma unroll
    for (int k = 0; k < HH; k++) acc += h[k] * outW[k * PP + p];
    out[gidx] = acc;
}

extern "C" void kernel_launch(void* const* d_in, const int* in_sizes, int n_in,
                              void* d_out, int out_size) {
    const float* x     = (const float*)d_in[0];
    const float* adj   = (const float*)d_in[1];
    const float* gcWi0 = (const float*)d_in[2];
    const float* gcbi0 = (const float*)d_in[3];
    const float* gcWh0 = (const float*)d_in[4];
    const float* gcbh0 = (const float*)d_in[5];
    const float* liWi0 = (const float*)d_in[6];
    const float* libi0 = (const float*)d_in[7];
    const float* liWh0 = (const float*)d_in[8];
    const float* libh0 = (const float*)d_in[9];
    const float* gcWi1 = (const float*)d_in[10];
    const float* gcbi1 = (const float*)d_in[11];
    const float* gcWh1 = (const float*)d_in[12];
    const float* gcbh1 = (const float*)d_in[13];
    const float* liWi1 = (const float*)d_in[14];
    const float* libi1 = (const float*)d_in[15];
    const float* liWh1 = (const float*)d_in[16];
    const float* libh1 = (const float*)d_in[17];
    const float* outW  = (const float*)d_in[18];
    const float* outb  = (const float*)d_in[19];
    float* out = (float*)d_out;

    static int smem_set = 0;
    if (!smem_set) {
        cudaFuncSetAttribute(k_fused, cudaFuncAttributeMaxDynamicSharedMemorySize, SMEM_FUSED);
        smem_set = 1;
    }

    k_degprep<<<4096, 256>>>(adj, x, gcWi0, gcbi0, gcWh0, gcbh0, liWi0, libi0, liWh0, libh0,
                             gcWi1, gcbi1, gcWh1, gcbh1, liWi1, libi1, liWh1, libh1);
    k_scan<<<1, 1024>>>();
    k_fillx<<<NN, 256>>>(adj, x);
    for (int t = 0; t < TT; t++) {
        k_fused<<<NN / RPB, NTH, SMEM_FUSED>>>(x, t);
    }
    k_out<<<(NN * PP + 255) / 256, 256>>>(outW, outb, out);
}

// round 15
// speedup vs baseline: 1.0183x; 1.0151x over previous
#include <cuda_runtime.h>
#include <math.h>

#define NN 4096
#define HH 64
#define HC 128          // concatenated row width: [h0(64) | h1(64)]
#define G4 256
#define TT 48
#define INP 2
#define PP 12
#define RPB 16          // rows per block
#define NTH 384         // 12 warps: 4 slots x 3 balanced GEMM tasks
#define ZS 36           // shared z stride per k in floats (32 dup + 4 pad) -> 18 ull (EVEN)
#define ZROWS 260       // h0(64) Ah0(64) x(4) h1(64) Ah1(64)
#define CMB (RPB * G4)  // one comb partial: 4096 floats
#define SMEM_FUSED ((ZROWS * ZS + 3 * CMB) * 4)   // z (36.6KB) + 3 comb (48KB) = 84.6KB
#define MAXNNZ (1 << 21)

typedef unsigned long long ull;

// ---------------- static device scratch ----------------
__device__ float d_hcat[2][NN * HC];        // ping-pong [h0 | h1] per node
__device__ float d_c0[NN * HH];
__device__ float d_c1[NN * HH];
__device__ float d_Xall[NN * (TT * INP)];   // [n][t*2+k]
__device__ float d_AX[NN * (TT * INP)];     // A @ Xall
// W1 rows (z-aligned): 0..63 liWi1 (h0), 64..127 gcWi1 (Ah0), 128..191 liWh1 (h1), 192..255 gcWh1 (Ah1)
__device__ float d_W1[256 * G4];
// W0 rows (z-aligned): 0..63 liWh0 (h0), 64..127 gcWh0 (Ah0), 128..129 liWi0 (x), 130..131 gcWi0 (Ax)
__device__ float d_W0[132 * G4];
__device__ float d_b0[G4];
__device__ float d_b1[G4];
__device__ int   d_rowcnt[NN];
__device__ int   d_rowptr[NN + 1];
__device__ float d_dinv[NN];
__device__ int   d_col[MAXNNZ];
__device__ float d_val[MAXNNZ];

// ---------------- helpers ----------------
__device__ __forceinline__ ull fma2(ull a, ull b, ull c) {
    ull d;
    asm("fma.rn.f32x2 %0, %1, %2, %3;" : "=l"(d) : "l"(a), "l"(b), "l"(c));
    return d;
}
__device__ __forceinline__ float sigf(float v) {
    return __fdividef(1.f, 1.f + __expf(-v));
}
__device__ __forceinline__ float tanhfast(float v) {
    return __fmaf_rn(2.f, __fdividef(1.f, 1.f + __expf(-2.f * v)), -1.f);
}

// ---------------- setup kernel 1: degree count + all prep work ----------------
__global__ void k_degprep(const float* __restrict__ adj, const float* __restrict__ x,
                          const float* __restrict__ gcWi0, const float* __restrict__ gcbi0,
                          const float* __restrict__ gcWh0, const float* __restrict__ gcbh0,
                          const float* __restrict__ liWi0, const float* __restrict__ libi0,
                          const float* __restrict__ liWh0, const float* __restrict__ libh0,
                          const float* __restrict__ gcWi1, const float* __restrict__ gcbi1,
                          const float* __restrict__ gcWh1, const float* __restrict__ gcbh1,
                          const float* __restrict__ liWi1, const float* __restrict__ libi1,
                          const float* __restrict__ liWh1, const float* __restrict__ libh1) {
    int i = blockIdx.x;
    int tid = threadIdx.x;
    // ---- degree + nnz count for row i ----
    {
        const float* row = adj + (size_t)i * NN;
        int cnt = 0; float deg = 0.f;
        for (int j = tid; j < NN; j += 256) {
            float a = row[j];
            if (j == i) a += 1.f;
            if (a != 0.f) { cnt++; deg += a; }
        }
        __shared__ int   scnt[256];
        __shared__ float sdeg[256];
        scnt[tid] = cnt; sdeg[tid] = deg;
        __syncthreads();
        for (int s = 128; s > 0; s >>= 1) {
            if (tid < s) { scnt[tid] += scnt[tid + s]; sdeg[tid] += sdeg[tid + s]; }
            __syncthreads();
        }
        if (tid == 0) {
            d_rowcnt[i] = scnt[0];
            d_dinv[i] = rsqrtf(sdeg[0]);
        }
    }
    // ---- prep work (grid covers 1M ids) ----
    int id = i * 256 + tid;
    if (id < NN * (TT * INP)) {
        int n = id / (TT * INP), c = id % (TT * INP);
        int t = c >> 1, k = c & 1;
        d_Xall[id] = x[t * (NN * INP) + n * INP + k];
    }
    if (id < NN * HC) {
        d_hcat[0][id] = 0.f;        // h1 half matters; h0 half overwritten later
    }
    if (id < NN * HH) {
        d_c1[id] = 0.f;
    }
    if (id < 256 * G4) {
        int k = id >> 8, c = id & 255;
        float w1;
        if (k < 64)       w1 = liWi1[k * G4 + c];          // z: h0
        else if (k < 128) w1 = gcWi1[(k - 64) * G4 + c];   // z: A@h0
        else if (k < 192) w1 = liWh1[(k - 128) * G4 + c];  // z: h1
        else              w1 = gcWh1[(k - 192) * G4 + c];  // z: A@h1
        d_W1[id] = w1;
        if (k < 132) {
            float w0;
            if (k < 64)       w0 = liWh0[k * G4 + c];          // z: h0
            else if (k < 128) w0 = gcWh0[(k - 64) * G4 + c];   // z: A@h0
            else if (k < 130) w0 = liWi0[(k - 128) * G4 + c];  // z: x
            else              w0 = gcWi0[(k - 130) * G4 + c];  // z: Ax
            d_W0[k * G4 + c] = w0;
        }
        if (id < G4) {
            d_b0[id] = gcbi0[id] + gcbh0[id] + libi0[id] + libh0[id];
            d_b1[id] = gcbi1[id] + gcbh1[id] + libi1[id] + libh1[id];
        }
    }
}

// ---------------- setup kernel 2: exclusive scan ----------------
__global__ void k_scan() {
    __shared__ int ssum[1024];
    int t = threadIdx.x;
    int c0 = d_rowcnt[4 * t], c1 = d_rowcnt[4 * t + 1],
        c2 = d_rowcnt[4 * t + 2], c3 = d_rowcnt[4 * t + 3];
    int s = c0 + c1 + c2 + c3;
    ssum[t] = s;
    __syncthreads();
    for (int off = 1; off < 1024; off <<= 1) {
        int v = (t >= off) ? ssum[t - off] : 0;
        __syncthreads();
        ssum[t] += v;
        __syncthreads();
    }
    int excl = ssum[t] - s;
    d_rowptr[4 * t]     = excl;
    d_rowptr[4 * t + 1] = excl + c0;
    d_rowptr[4 * t + 2] = excl + c0 + c1;
    d_rowptr[4 * t + 3] = excl + c0 + c1 + c2;
    if (t == 1023) d_rowptr[NN] = ssum[1023];
}

// ---------------- setup kernel 3: CSR fill + AX spmm (own row) + first-step cell0 ----------------
__global__ void k_fillx(const float* __restrict__ adj, const float* __restrict__ x) {
    int i = blockIdx.x;
    int tid = threadIdx.x;
    const float* row = adj + (size_t)i * NN;
    float di = d_dinv[i];
    int cnt = 0;
    for (int j = tid * 16; j < tid * 16 + 16; j++) {
        float a = row[j] + ((j == i) ? 1.f : 0.f);
        if (a != 0.f) cnt++;
    }
    __shared__ int soff[256];
    __shared__ float sax[2];
    soff[tid] = cnt;
    __syncthreads();
    for (int off = 1; off < 256; off <<= 1) {
        int v = (tid >= off) ? soff[tid - off] : 0;
        __syncthreads();
        soff[tid] += v;
        __syncthreads();
    }
    int pos = d_rowptr[i] + soff[tid] - cnt;
    for (int j = tid * 16; j < tid * 16 + 16; j++) {
        float a = row[j] + ((j == i) ? 1.f : 0.f);
        if (a != 0.f) {
            d_col[pos] = j;
            d_val[pos] = di * a * d_dinv[j];
            pos++;
        }
    }
    __syncthreads();   // row i's CSR fully written, visible to this block

    // ---- AX row i (threads 0..95) ----
    if (tid < TT * INP) {
        int p0 = d_rowptr[i], p1 = d_rowptr[i + 1];
        float acc = 0.f;
        for (int p = p0; p < p1; p++) {
            acc += d_val[p] * d_Xall[d_col[p] * (TT * INP) + tid];
        }
        d_AX[i * (TT * INP) + tid] = acc;
        if (tid < 2) sax[tid] = acc;
    }
    __syncthreads();

    // ---- first-step cell0 for node i (h0=Ah0=0 so comb = b0 + x-part) ----
    if (tid < HH) {
        int j = tid;
        float x0  = x[i * INP];
        float x1  = x[i * INP + 1];
        float ax0 = sax[0];
        float ax1 = sax[1];
        float gv[4];
        #pragma unroll
        for (int q = 0; q < 4; q++) {
            int c = q * 64 + j;
            gv[q] = d_b0[c]
                  + x0  * d_W0[128 * G4 + c] + x1  * d_W0[129 * G4 + c]
                  + ax0 * d_W0[130 * G4 + c] + ax1 * d_W0[131 * G4 + c];
        }
        float nc = sigf(gv[0]) * tanhfast(gv[3]);
        float nh = sigf(gv[2]) * tanhfast(nc);
        d_c0[i * HH + j] = nc;
        d_hcat[0][i * HC + j] = nh;
    }
}

// ---------------- GEMM partial: 4 warp-slots of 8 rows x 128 cols ----------------
// ws in [0,4): rows r0=(ws&1)*8 .. +7, cols c0=(ws>>1)*128 + lane*4 .. +3
// Per warp-k: 1 LDG.128 (W, 2 col-pairs) + 4 ull2 broadcast LDS (8 z rows) + 16 FFMA2.
template <int KN, bool BIAS>
__device__ __forceinline__ void gemm_part8(const float* __restrict__ sh, float* __restrict__ comb,
                                           const float* __restrict__ W,
                                           const float* __restrict__ bb,
                                           int zrow0, int ws, int lane) {
    int r0 = (ws & 1) << 3;
    int c0 = ((ws >> 1) << 7) + (lane << 2);
    const float* Wp = W + c0;
    const ull* zz = (const ull*)sh + zrow0 * 18 + r0;

    ull ax[8], ay[8];
    if (BIAS) {
        ulonglong2 b2 = *(const ulonglong2*)(bb + c0);
        #pragma unroll
        for (int i = 0; i < 8; i++) { ax[i] = b2.x; ay[i] = b2.y; }
    } else {
        #pragma unroll
        for (int i = 0; i < 8; i++) { ax[i] = 0ull; ay[i] = 0ull; }
    }

    #pragma unroll 2
    for (int k = 0; k < KN; k++) {
        ulonglong2 w2 = *(const ulonglong2*)(Wp + k * G4);
        ulonglong2 zA = *(const ulonglong2*)(zz + k * 18);       // rows r0, r0+1
        ulonglong2 zB = *(const ulonglong2*)(zz + k * 18 + 2);   // rows r0+2, r0+3
        ax[0] = fma2(zA.x, w2.x, ax[0]); ay[0] = fma2(zA.x, w2.y, ay[0]);
        ax[1] = fma2(zA.y, w2.x, ax[1]); ay[1] = fma2(zA.y, w2.y, ay[1]);
        ax[2] = fma2(zB.x, w2.x, ax[2]); ay[2] = fma2(zB.x, w2.y, ay[2]);
        ax[3] = fma2(zB.y, w2.x, ax[3]); ay[3] = fma2(zB.y, w2.y, ay[3]);
        ulonglong2 zC = *(const ulonglong2*)(zz + k * 18 + 4);   // rows r0+4, r0+5
        ulonglong2 zD = *(const ulonglong2*)(zz + k * 18 + 6);   // rows r0+6, r0+7
        ax[4] = fma2(zC.x, w2.x, ax[4]); ay[4] = fma2(zC.x, w2.y, ay[4]);
        ax[5] = fma2(zC.y, w2.x, ax[5]); ay[5] = fma2(zC.y, w2.y, ay[5]);
        ax[6] = fma2(zD.x, w2.x, ax[6]); ay[6] = fma2(zD.x, w2.y, ay[6]);
        ax[7] = fma2(zD.y, w2.x, ax[7]); ay[7] = fma2(zD.y, w2.y, ay[7]);
    }
    float* base = comb + r0 * G4 + c0;
    #pragma unroll
    for (int i = 0; i < 8; i++) {
        *(ulonglong2*)(base + i * G4) = make_ulonglong2(ax[i], ay[i]);
    }
}

// ---------------- fused step: cell1(t) + cell0(t+1), single GEMM phase ----------------
// z rows: 0..63 h0 | 64..127 A@h0 | 128..131 x(t+1),Ax(t+1) | 132..195 h1 | 196..259 A@h1
__global__ void __launch_bounds__(NTH, 2) k_fused(const float* __restrict__ x, int t) {
    extern __shared__ float sh[];
    float* combA = sh + ZROWS * ZS;     // cell1 k-half0 (with bias)
    float* combB = combA + CMB;         // cell1 k-half1
    float* combC = combA + 2 * CMB;     // cell0 full K (with bias)
    int tid = threadIdx.x;
    int n0 = blockIdx.x * RPB;
    int cur = t & 1, nxt = cur ^ 1;
    const float* __restrict__ g = d_hcat[cur];
    int w = tid >> 5, lane = tid & 31;
    bool more = (t + 1 < TT);

    // ---- phase 1: stage plain z + x, and gather ----
    for (int e = tid; e < RPB * HH; e += NTH) {     // 1024 = 16 rows x 64 k
        int r = e >> 6, k = e & 63;
        float v0 = g[(n0 + r) * HC + k];        // h0 -> row k
        float v1 = g[(n0 + r) * HC + 64 + k];   // h1 -> row 132+k
        *(float2*)(sh + k * ZS + 2 * r)         = make_float2(v0, v0);
        *(float2*)(sh + (132 + k) * ZS + 2 * r) = make_float2(v1, v1);
    }
    if (more && tid < RPB) {
        int n = n0 + tid;
        float x0  = x[(t + 1) * (NN * INP) + n * INP];
        float x1  = x[(t + 1) * (NN * INP) + n * INP + 1];
        float ax0 = d_AX[n * (TT * INP) + 2 * (t + 1)];
        float ax1 = d_AX[n * (TT * INP) + 2 * (t + 1) + 1];
        *(float2*)(sh + 128 * ZS + 2 * tid) = make_float2(x0, x0);
        *(float2*)(sh + 129 * ZS + 2 * tid) = make_float2(x1, x1);
        *(float2*)(sh + 130 * ZS + 2 * tid) = make_float2(ax0, ax0);
        *(float2*)(sh + 131 * ZS + 2 * tid) = make_float2(ax1, ax1);
    }
    // gather: 12 warps over 16 rows; lane<16 -> A@h0 (rows 64+4l), lane>=16 -> A@h1 (rows 132+4l)
    {
        int koff = (lane < 16) ? (64 + 4 * lane) : (132 + 4 * lane);
        const float* gl = g + 4 * lane;
        for (int rr = w; rr < RPB; rr += 12) {
            int n = n0 + rr;
            int p = d_rowptr[n], p1 = d_rowptr[n + 1];
            float a0 = 0.f, a1 = 0.f, a2 = 0.f, a3 = 0.f;
            for (; p + 4 <= p1; p += 4) {
                int   m0 = d_col[p],     m1 = d_col[p + 1];
                int   m2 = d_col[p + 2], m3 = d_col[p + 3];
                float v0 = d_val[p],     v1 = d_val[p + 1];
                float v2 = d_val[p + 2], v3 = d_val[p + 3];
                float4 A = *(const float4*)(gl + m0 * HC);
                float4 B = *(const float4*)(gl + m1 * HC);
                float4 C = *(const float4*)(gl + m2 * HC);
                float4 D = *(const float4*)(gl + m3 * HC);
                a0 += v0 * A.x; a1 += v0 * A.y; a2 += v0 * A.z; a3 += v0 * A.w;
                a0 += v1 * B.x; a1 += v1 * B.y; a2 += v1 * B.z; a3 += v1 * B.w;
                a0 += v2 * C.x; a1 += v2 * C.y; a2 += v2 * C.z; a3 += v2 * C.w;
                a0 += v3 * D.x; a1 += v3 * D.y; a2 += v3 * D.z; a3 += v3 * D.w;
            }
            for (; p < p1; p++) {
                int m = d_col[p];
                float v = d_val[p];
                float4 A = *(const float4*)(gl + m * HC);
                a0 += v * A.x; a1 += v * A.y; a2 += v * A.z; a3 += v * A.w;
            }
            *(float2*)(sh + (koff + 0) * ZS + 2 * rr) = make_float2(a0, a0);
            *(float2*)(sh + (koff + 1) * ZS + 2 * rr) = make_float2(a1, a1);
            *(float2*)(sh + (koff + 2) * ZS + 2 * rr) = make_float2(a2, a2);
            *(float2*)(sh + (koff + 3) * ZS + 2 * rr) = make_float2(a3, a3);
        }
    }
    __syncthreads();

    // ---- phase 2: 12 balanced GEMM tasks (4 slots x {cell1-h0, cell1-h1, cell0-full}) ----
    {
        int task = w >> 2, ws = w & 3;
        if (task == 0) {
            gemm_part8<128, true>(sh, combA, d_W1, d_b1, 0, ws, lane);
        } else if (task == 1) {
            gemm_part8<128, false>(sh, combB, d_W1 + 128 * G4, (const float*)0, 132, ws, lane);
        } else if (more) {
            gemm_part8<132, true>(sh, combC, d_W0, d_b0, 0, ws, lane);
        }
    }
    __syncthreads();

    // ---- phase 3: gates for both cells ----
    for (int e = tid; e < RPB * HH; e += NTH) {     // 1024 = 16 rows * 64
        int r = e >> 6, j = e & 63;
        float ig = combA[r * G4 + j]       + combB[r * G4 + j];
        float fg = combA[r * G4 + 64 + j]  + combB[r * G4 + 64 + j];
        float og = combA[r * G4 + 128 + j] + combB[r * G4 + 128 + j];
        float gg = combA[r * G4 + 192 + j] + combB[r * G4 + 192 + j];
        int n = n0 + r;
        float cold = d_c1[n * HH + j];
        float nc = sigf(fg) * cold + sigf(ig) * tanhfast(gg);
        float nh = sigf(og) * tanhfast(nc);
        d_c1[n * HH + j] = nc;
        d_hcat[nxt][n * HC + 64 + j] = nh;
    }
    if (more) {
        for (int e = tid; e < RPB * HH; e += NTH) {
            int r = e >> 6, j = e & 63;
            float ig = combC[r * G4 + j];
            float fg = combC[r * G4 + 64 + j];
            float og = combC[r * G4 + 128 + j];
            float gg = combC[r * G4 + 192 + j];
            int n = n0 + r;
            float cold = d_c0[n * HH + j];
            float nc = sigf(fg) * cold + sigf(ig) * tanhfast(gg);
            float nh = sigf(og) * tanhfast(nc);
            d_c0[n * HH + j] = nc;
            d_hcat[nxt][n * HC + j] = nh;
        }
    }
}

// ---------------- output projection ----------------
__global__ void k_out(const float* __restrict__ outW, const float* __restrict__ outb,
                      float* __restrict__ out) {
    int gidx = blockIdx.x * blockDim.x + threadIdx.x;
    if (gidx >= NN * PP) return;
    int n = gidx / PP, p = gidx % PP;
    const float* h = d_hcat[TT & 1] + n * HC + 64;
    float acc = outb[p];
    #pragma unroll
    for (int k = 0; k < HH; k++) acc += h[k] * outW[k * PP + p];
    out[gidx] = acc;
}

extern "C" void kernel_launch(void* const* d_in, const int* in_sizes, int n_in,
                              void* d_out, int out_size) {
    const float* x     = (const float*)d_in[0];
    const float* adj   = (const float*)d_in[1];
    const float* gcWi0 = (const float*)d_in[2];
    const float* gcbi0 = (const float*)d_in[3];
    const float* gcWh0 = (const float*)d_in[4];
    const float* gcbh0 = (const float*)d_in[5];
    const float* liWi0 = (const float*)d_in[6];
    const float* libi0 = (const float*)d_in[7];
    const float* liWh0 = (const float*)d_in[8];
    const float* libh0 = (const float*)d_in[9];
    const float* gcWi1 = (const float*)d_in[10];
    const float* gcbi1 = (const float*)d_in[11];
    const float* gcWh1 = (const float*)d_in[12];
    const float* gcbh1 = (const float*)d_in[13];
    const float* liWi1 = (const float*)d_in[14];
    const float* libi1 = (const float*)d_in[15];
    const float* liWh1 = (const float*)d_in[16];
    const float* libh1 = (const float*)d_in[17];
    const float* outW  = (const float*)d_in[18];
    const float* outb  = (const float*)d_in[19];
    float* out = (float*)d_out;

    static int smem_set = 0;
    if (!smem_set) {
        cudaFuncSetAttribute(k_fused, cudaFuncAttributeMaxDynamicSharedMemorySize, SMEM_FUSED);
        smem_set = 1;
    }

    k_degprep<<<4096, 256>>>(adj, x, gcWi0, gcbi0, gcWh0, gcbh0, liWi0, libi0, liWh0, libh0,
                             gcWi1, gcbi1, gcWh1, gcbh1, liWi1, libi1, liWh1, libh1);
    k_scan<<<1, 1024>>>();
    k_fillx<<<NN, 256>>>(adj, x);
    for (int t = 0; t < TT; t++) {
        k_fused<<<NN / RPB, NTH, SMEM_FUSED>>>(x, t);
    }
    k_out<<<(NN * PP + 255) / 256, 256>>>(outW, outb, out);
}